// round 11
// baseline (speedup 1.0000x reference)
#include <cuda_runtime.h>
#include <math.h>
#include <stdint.h>

#define NROWS 65536   // B*S = 8*8192
#define EDIM  256
#define NQ    8
#define FDIM  264     // NQ + EDIM

// ---------------------------------------------------------------------------
// Fused kernel: out[n,e] = sum_f y[n,f]*W2[e,f] + b2[e],  y = [z | x]
// where z = circuit_expvals(x @ W1^T + b1 + qw) is computed IN-KERNEL from
// the x data already streaming through the GEMM's A-prefetch registers.
//
// tf32 mma.sync.m16n8k8, CTA 128x128, 8 warps (2x4), warp tile 64x32.
// 16 stages of BK=16 (two BK=8/PADK=12 sub-tiles) cover x blocks 0..31
// (F cols 8..263); the z block (F cols 0..7) is built and multiplied LAST.
//
// xq accumulation: thread (row pair lr, half h=lc/4) owns j = lc..lc+3 and
// accumulates over ALL k: own av quad + partner quad via shfl_xor(1).
// W1 reads are warp-broadcast LDG (L1-resident, ~1 wavefront each).
// ---------------------------------------------------------------------------
#define BM 128
#define BN 128
#define BK 8
#define PADK 12

// tf32 is a b32-typed value in PTX: destination must be a .b32 register.
__device__ __forceinline__ uint32_t to_tf32(float v) {
    uint32_t r;
    asm("cvt.rna.tf32.f32 %0, %1;" : "=r"(r) : "f"(v));
    return r;
}
__device__ __forceinline__ float to_tf32f(float v) {
    return __uint_as_float(to_tf32(v));
}
__device__ __forceinline__ float4 cvt4(float4 v) {
    return make_float4(to_tf32f(v.x), to_tf32f(v.y), to_tf32f(v.z), to_tf32f(v.w));
}

__device__ __forceinline__ void mma_tf32(float* d, const uint32_t* a, const uint32_t* b) {
    asm volatile(
        "mma.sync.aligned.m16n8k8.row.col.f32.tf32.tf32.f32 "
        "{%0,%1,%2,%3},{%4,%5,%6,%7},{%8,%9},{%0,%1,%2,%3};"
        : "+f"(d[0]), "+f"(d[1]), "+f"(d[2]), "+f"(d[3])
        : "r"(a[0]), "r"(a[1]), "r"(a[2]), "r"(a[3]), "r"(b[0]), "r"(b[1]));
}

__global__ __launch_bounds__(256, 2) void fused_kernel(
    const float* __restrict__ x,  const float* __restrict__ W1,
    const float* __restrict__ b1, const float* __restrict__ qw,
    const float* __restrict__ W2, const float* __restrict__ b2,
    float* __restrict__ out)
{
    // [stage][sub][row][k] — 48 KB total (A+B)
    __shared__ __align__(16) float As[2][2][BM][PADK];
    __shared__ __align__(16) float Bs[2][2][BN][PADK];

    int tid  = threadIdx.x;
    int wid  = tid >> 5;
    int lane = tid & 31;
    int g    = lane >> 2;   // 0..7
    int q    = lane & 3;    // 0..3

    int warp_m = (wid & 1) * 64;   // 0 or 64
    int warp_n = (wid >> 1) * 32;  // 0,32,64,96

    int rowBase = blockIdx.x * BM;
    int colBase = blockIdx.y * BN;

    int lr  = tid >> 1;          // 0..127
    int lc  = (tid & 1) * 4;     // 0 or 4
    int lcx = lc ^ 4;

    const float* Ax = x  + (size_t)(rowBase + lr) * EDIM + lc;
    const float* Bw = W2 + (size_t)(colBase + lr) * FDIM + lc;

    float acc[4][4][4];
#pragma unroll
    for (int i = 0; i < 4; i++)
#pragma unroll
        for (int j = 0; j < 4; j++)
#pragma unroll
            for (int v = 0; v < 4; v++) acc[i][j][v] = 0.f;

    float xqp[4] = {0.f, 0.f, 0.f, 0.f};   // partial xq for j = lc..lc+3

    // accumulate xq contribution of one raw x quad (cols kb+lc..kb+lc+3)
    // plus the partner thread's quad (cols kb+lcx..) via shfl.
#define ACCUM_XQ(av, kb) do {                                              \
        float px = __shfl_xor_sync(0xffffffffu, (av).x, 1);                \
        float py = __shfl_xor_sync(0xffffffffu, (av).y, 1);                \
        float pz = __shfl_xor_sync(0xffffffffu, (av).z, 1);                \
        float pw = __shfl_xor_sync(0xffffffffu, (av).w, 1);                \
        _Pragma("unroll")                                                  \
        for (int j = 0; j < 4; j++) {                                      \
            const float* wr = W1 + (lc + j) * EDIM + (kb);                 \
            float4 wo = __ldg((const float4*)(wr + lc));                   \
            float4 wp = __ldg((const float4*)(wr + lcx));                  \
            xqp[j] += (av).x * wo.x + (av).y * wo.y                        \
                    + (av).z * wo.z + (av).w * wo.w                        \
                    + px * wp.x + py * wp.y + pz * wp.z + pw * wp.w;       \
        }                                                                  \
    } while (0)

    // ---- prologue: stage 0 = x blocks 0,1 (F blocks 1,2) ----
    {
        float4 a0 = *reinterpret_cast<const float4*>(Ax);
        float4 a1 = *reinterpret_cast<const float4*>(Ax + BK);
        float4 b0 = *reinterpret_cast<const float4*>(Bw + BK);
        float4 b1v = *reinterpret_cast<const float4*>(Bw + 2 * BK);
        ACCUM_XQ(a0, 0);
        ACCUM_XQ(a1, BK);
        *reinterpret_cast<float4*>(&As[0][0][lr][lc]) = cvt4(a0);
        *reinterpret_cast<float4*>(&As[0][1][lr][lc]) = cvt4(a1);
        *reinterpret_cast<float4*>(&Bs[0][0][lr][lc]) = cvt4(b0);
        *reinterpret_cast<float4*>(&Bs[0][1][lr][lc]) = cvt4(b1v);
    }
    __syncthreads();

    // ---- main loop: stage s = x blocks 2s, 2s+1 ----
    for (int s = 0; s < 16; s++) {
        int cur = s & 1;
        int nxt = cur ^ 1;
        bool has_next = (s < 15);

        float4 pa0, pa1, pb0, pb1;
        if (has_next) {   // load stage s+1 = x blocks 2s+2, 2s+3
            pa0 = *reinterpret_cast<const float4*>(Ax + (2 * s + 2) * BK);
            pa1 = *reinterpret_cast<const float4*>(Ax + (2 * s + 3) * BK);
            pb0 = *reinterpret_cast<const float4*>(Bw + (2 * s + 3) * BK);
            pb1 = *reinterpret_cast<const float4*>(Bw + (2 * s + 4) * BK);
            ACCUM_XQ(pa0, (2 * s + 2) * BK);
            ACCUM_XQ(pa1, (2 * s + 3) * BK);
        }

#pragma unroll
        for (int sub = 0; sub < 2; sub++) {
            uint32_t afr[4][4], bfr[4][2];
#pragma unroll
            for (int ma = 0; ma < 4; ma++) {
                int r0 = warp_m + ma * 16 + g;
                afr[ma][0] = __float_as_uint(As[cur][sub][r0    ][q    ]);
                afr[ma][1] = __float_as_uint(As[cur][sub][r0 + 8][q    ]);
                afr[ma][2] = __float_as_uint(As[cur][sub][r0    ][q + 4]);
                afr[ma][3] = __float_as_uint(As[cur][sub][r0 + 8][q + 4]);
            }
#pragma unroll
            for (int nb = 0; nb < 4; nb++) {
                int c0 = warp_n + nb * 8 + g;
                bfr[nb][0] = __float_as_uint(Bs[cur][sub][c0][q    ]);
                bfr[nb][1] = __float_as_uint(Bs[cur][sub][c0][q + 4]);
            }
#pragma unroll
            for (int ma = 0; ma < 4; ma++)
#pragma unroll
                for (int nb = 0; nb < 4; nb++)
                    mma_tf32(acc[ma][nb], afr[ma], bfr[nb]);
        }

        if (has_next) {
            *reinterpret_cast<float4*>(&As[nxt][0][lr][lc]) = cvt4(pa0);
            *reinterpret_cast<float4*>(&As[nxt][1][lr][lc]) = cvt4(pa1);
            *reinterpret_cast<float4*>(&Bs[nxt][0][lr][lc]) = cvt4(pb0);
            *reinterpret_cast<float4*>(&Bs[nxt][1][lr][lc]) = cvt4(pb1);
            __syncthreads();
        }
    }

    // ---- z stage: build z tile in buf0 (free since stage-14 sync) ----
    // scratch (cos values) aliases As[0][1]; z A-tile goes to As[0][0].
    {
        float4 cv;
        cv.x = cosf(xqp[0] + __ldg(b1 + lc + 0) + __ldg(qw + lc + 0));
        cv.y = cosf(xqp[1] + __ldg(b1 + lc + 1) + __ldg(qw + lc + 1));
        cv.z = cosf(xqp[2] + __ldg(b1 + lc + 2) + __ldg(qw + lc + 2));
        cv.w = cosf(xqp[3] + __ldg(b1 + lc + 3) + __ldg(qw + lc + 3));
        float4* sc4 = reinterpret_cast<float4*>(&As[0][1][0][0]);
        sc4[lr * 2 + (tid & 1)] = cv;

        // B tile for F block 0 (z columns of W2) — L2-hot
        float4 pbz = *reinterpret_cast<const float4*>(Bw);
        *reinterpret_cast<float4*>(&Bs[0][0][lr][lc]) = cvt4(pbz);
    }
    __syncthreads();

    if (tid < 128) {
        const float4* sc4 = reinterpret_cast<const float4*>(&As[0][1][0][0]);
        float4 cA = sc4[tid * 2];
        float4 cB = sc4[tid * 2 + 1];
        float c[NQ] = {cA.x, cA.y, cA.z, cA.w, cB.x, cB.y, cB.z, cB.w};
        float zv[NQ];
        float sfx = c[1];
#pragma unroll
        for (int i = 2; i < NQ; i++) sfx *= c[i];
        zv[0] = sfx;                      // z0 = prod_{i=1..7} c_i
        float r = c[0];
#pragma unroll
        for (int k = 1; k < NQ; k++) { r *= c[k]; zv[k] = r; }
        *reinterpret_cast<float4*>(&As[0][0][tid][0]) =
            make_float4(to_tf32f(zv[0]), to_tf32f(zv[1]), to_tf32f(zv[2]), to_tf32f(zv[3]));
        *reinterpret_cast<float4*>(&As[0][0][tid][4]) =
            make_float4(to_tf32f(zv[4]), to_tf32f(zv[5]), to_tf32f(zv[6]), to_tf32f(zv[7]));
    }
    __syncthreads();

    // z-block MMA (buf 0, sub 0)
    {
        uint32_t afr[4][4], bfr[4][2];
#pragma unroll
        for (int ma = 0; ma < 4; ma++) {
            int r0 = warp_m + ma * 16 + g;
            afr[ma][0] = __float_as_uint(As[0][0][r0    ][q    ]);
            afr[ma][1] = __float_as_uint(As[0][0][r0 + 8][q    ]);
            afr[ma][2] = __float_as_uint(As[0][0][r0    ][q + 4]);
            afr[ma][3] = __float_as_uint(As[0][0][r0 + 8][q + 4]);
        }
#pragma unroll
        for (int nb = 0; nb < 4; nb++) {
            int c0 = warp_n + nb * 8 + g;
            bfr[nb][0] = __float_as_uint(Bs[0][0][c0][q    ]);
            bfr[nb][1] = __float_as_uint(Bs[0][0][c0][q + 4]);
        }
#pragma unroll
        for (int ma = 0; ma < 4; ma++)
#pragma unroll
            for (int nb = 0; nb < 4; nb++)
                mma_tf32(acc[ma][nb], afr[ma], bfr[nb]);
    }

    // epilogue: bias + store. c0,c1 at (g, 2q..2q+1); c2,c3 at (g+8, ...)
#pragma unroll
    for (int ma = 0; ma < 4; ma++) {
#pragma unroll
        for (int nb = 0; nb < 4; nb++) {
            int col  = colBase + warp_n + nb * 8 + 2 * q;
            int row0 = rowBase + warp_m + ma * 16 + g;
            float bias0 = __ldg(b2 + col);
            float bias1 = __ldg(b2 + col + 1);
            float2 v0 = make_float2(acc[ma][nb][0] + bias0, acc[ma][nb][1] + bias1);
            float2 v1 = make_float2(acc[ma][nb][2] + bias0, acc[ma][nb][3] + bias1);
            *reinterpret_cast<float2*>(out + (size_t)row0 * EDIM + col)       = v0;
            *reinterpret_cast<float2*>(out + (size_t)(row0 + 8) * EDIM + col) = v1;
        }
    }
}

// ---------------------------------------------------------------------------
extern "C" void kernel_launch(void* const* d_in, const int* in_sizes, int n_in,
                              void* d_out, int out_size) {
    const float* x  = (const float*)d_in[0];
    const float* W1 = (const float*)d_in[1];
    const float* b1 = (const float*)d_in[2];
    const float* qw = (const float*)d_in[3];
    const float* W2 = (const float*)d_in[4];
    const float* b2 = (const float*)d_in[5];
    float* out = (float*)d_out;

    dim3 grid(NROWS / BM, EDIM / BN);
    fused_kernel<<<grid, 256>>>(x, W1, b1, qw, W2, b2, out);
}

// round 13
// speedup vs baseline: 1.4148x; 1.4148x over previous
#include <cuda_runtime.h>
#include <math.h>
#include <stdint.h>

#define NROWS 65536   // B*S = 8*8192
#define EDIM  256
#define NQ    8
#define FDIM  264     // NQ + EDIM

// scratch for quantum layer outputs z[row][q]
__device__ float g_z[(size_t)NROWS * NQ];

// ---------------------------------------------------------------------------
// Kernel A: z = circuit_expvals(x @ W1^T + b1 + qw)
// One warp processes 4 rows. 256 FMA/thread as before, but the reduction is
// a halving butterfly (31 shfls vs 160) and the cos/cumprod tail runs on all
// 32 lanes (1 cosf each + two width-8 shfl scans), not a 4-lane serial tail.
// ---------------------------------------------------------------------------
__global__ __launch_bounds__(256) void quantum_kernel(
    const float* __restrict__ x, const float* __restrict__ W1,
    const float* __restrict__ b1, const float* __restrict__ qw)
{
    int gwarp = (blockIdx.x * 256 + threadIdx.x) >> 5;
    int lane  = threadIdx.x & 31;
    int row0  = gwarp * 4;
    if (row0 >= NROWS) return;

    const float4* x4 = reinterpret_cast<const float4*>(x);
    float4 xa[4], xb[4];
#pragma unroll
    for (int r = 0; r < 4; r++) {
        const float4* rp = x4 + (size_t)(row0 + r) * (EDIM / 4);
        xa[r] = __ldg(rp + lane);
        xb[r] = __ldg(rp + 32 + lane);
    }

    // cur[r*8+q] = this lane's partial of xq[row0+r][q]
    float cur[32];
    const float4* w4 = reinterpret_cast<const float4*>(W1);  // [8][64] float4
#pragma unroll
    for (int q = 0; q < NQ; q++) {
        float4 wa = __ldg(w4 + q * 64 + lane);
        float4 wb = __ldg(w4 + q * 64 + 32 + lane);
#pragma unroll
        for (int r = 0; r < 4; r++) {
            float s = xa[r].x * wa.x + xa[r].y * wa.y + xa[r].z * wa.z + xa[r].w * wa.w;
            s      += xb[r].x * wb.x + xb[r].y * wb.y + xb[r].z * wb.z + xb[r].w * wb.w;
            cur[r * 8 + q] = s;
        }
    }

    // halving-butterfly reduce: 31 shfls; static indices + SEL (no dynamic
    // register indexing). After this, lane v's cur[0] = xq for value v.
#pragma unroll
    for (int off = 16; off >= 1; off >>= 1) {
        bool hi = (lane & off) != 0;
#pragma unroll
        for (int i = 0; i < off; i++) {
            float a = cur[i], b = cur[i + off];
            float send = hi ? a : b;     // half we don't keep
            float keep = hi ? b : a;
            cur[i] = keep + __shfl_xor_sync(0xffffffffu, send, off);
        }
    }

    // lane v: row = row0 + (v>>3), qubit q = v&7
    int q = lane & 7;
    float c = cosf(cur[0] + __ldg(b1 + q) + __ldg(qw + q));

    // inclusive prefix product within each 8-lane segment -> cumprod[q]
    float p = c;
#pragma unroll
    for (int d = 1; d < 8; d <<= 1) {
        float t = __shfl_up_sync(0xffffffffu, p, d, 8);
        if (q >= d) p *= t;
    }
    // same scan with c0 replaced by 1 -> lane 7 holds prod_{i=1..7} c_i
    float cp = (q == 0) ? 1.0f : c;
    float pp = cp;
#pragma unroll
    for (int d = 1; d < 8; d <<= 1) {
        float t = __shfl_up_sync(0xffffffffu, pp, d, 8);
        if (q >= d) pp *= t;
    }
    float z0 = __shfl_sync(0xffffffffu, pp, 7, 8);
    float z  = (q == 0) ? z0 : p;

    int row = row0 + (lane >> 3);
    g_z[(size_t)row * NQ + q] = z;   // warp writes 128 contiguous bytes
}

// ---------------------------------------------------------------------------
// Kernel B: (measured-best Round-9 GEMM, 96.2us) out = [z|x] @ W2^T + b2
// tf32 mma.sync.m16n8k8, CTA 128x128, 8 warps, warp tile 64x32.
// BK=16 stages = two BK=8/PADK=12 sub-tiles; 17 barriers; scalar prefetch.
// ---------------------------------------------------------------------------
#define BM 128
#define BN 128
#define BK 8
#define PADK 12

__device__ __forceinline__ uint32_t to_tf32(float v) {
    uint32_t r;
    asm("cvt.rna.tf32.f32 %0, %1;" : "=r"(r) : "f"(v));
    return r;
}
__device__ __forceinline__ float to_tf32f(float v) {
    return __uint_as_float(to_tf32(v));
}
__device__ __forceinline__ float4 cvt4(float4 v) {
    return make_float4(to_tf32f(v.x), to_tf32f(v.y), to_tf32f(v.z), to_tf32f(v.w));
}

__device__ __forceinline__ void mma_tf32(float* d, const uint32_t* a, const uint32_t* b) {
    asm volatile(
        "mma.sync.aligned.m16n8k8.row.col.f32.tf32.tf32.f32 "
        "{%0,%1,%2,%3},{%4,%5,%6,%7},{%8,%9},{%0,%1,%2,%3};"
        : "+f"(d[0]), "+f"(d[1]), "+f"(d[2]), "+f"(d[3])
        : "r"(a[0]), "r"(a[1]), "r"(a[2]), "r"(a[3]), "r"(b[0]), "r"(b[1]));
}

__global__ __launch_bounds__(256, 2) void gemm_kernel(
    const float* __restrict__ x, const float* __restrict__ W2,
    const float* __restrict__ b2, float* __restrict__ out)
{
    __shared__ __align__(16) float As[2][2][BM][PADK];
    __shared__ __align__(16) float Bs[2][2][BN][PADK];

    int tid  = threadIdx.x;
    int wid  = tid >> 5;
    int lane = tid & 31;
    int g    = lane >> 2;
    int q    = lane & 3;

    int warp_m = (wid & 1) * 64;
    int warp_n = (wid >> 1) * 32;

    int rowBase = blockIdx.x * BM;
    int colBase = blockIdx.y * BN;

    int lr = tid >> 1;
    int lc = (tid & 1) * 4;

    const float* Az = g_z + (size_t)(rowBase + lr) * NQ + lc;
    const float* Ax = x   + (size_t)(rowBase + lr) * EDIM + lc;
    const float* Bw = W2  + (size_t)(colBase + lr) * FDIM + lc;

    float acc[4][4][4];
#pragma unroll
    for (int i = 0; i < 4; i++)
#pragma unroll
        for (int j = 0; j < 4; j++)
#pragma unroll
            for (int v = 0; v < 4; v++) acc[i][j][v] = 0.f;

    // ---- pre-stage: F block 0 (z) into stage 0 / sub 0 ----
    {
        float4 av = cvt4(*reinterpret_cast<const float4*>(Az));
        float4 bv = cvt4(*reinterpret_cast<const float4*>(Bw));
        *reinterpret_cast<float4*>(&As[0][0][lr][lc]) = av;
        *reinterpret_cast<float4*>(&Bs[0][0][lr][lc]) = bv;
    }
    float4 pa0 = *reinterpret_cast<const float4*>(Ax);
    float4 pa1 = *reinterpret_cast<const float4*>(Ax + BK);
    float4 pb0 = *reinterpret_cast<const float4*>(Bw + BK);
    float4 pb1 = *reinterpret_cast<const float4*>(Bw + 2 * BK);
    __syncthreads();

    // compute pre-stage (sub 0 only)
    {
        uint32_t afr[4][4], bfr[4][2];
#pragma unroll
        for (int ma = 0; ma < 4; ma++) {
            int r0 = warp_m + ma * 16 + g;
            afr[ma][0] = __float_as_uint(As[0][0][r0    ][q    ]);
            afr[ma][1] = __float_as_uint(As[0][0][r0 + 8][q    ]);
            afr[ma][2] = __float_as_uint(As[0][0][r0    ][q + 4]);
            afr[ma][3] = __float_as_uint(As[0][0][r0 + 8][q + 4]);
        }
#pragma unroll
        for (int nb = 0; nb < 4; nb++) {
            int c0 = warp_n + nb * 8 + g;
            bfr[nb][0] = __float_as_uint(Bs[0][0][c0][q    ]);
            bfr[nb][1] = __float_as_uint(Bs[0][0][c0][q + 4]);
        }
#pragma unroll
        for (int ma = 0; ma < 4; ma++)
#pragma unroll
            for (int nb = 0; nb < 4; nb++)
                mma_tf32(acc[ma][nb], afr[ma], bfr[nb]);
    }
    *reinterpret_cast<float4*>(&As[1][0][lr][lc]) = cvt4(pa0);
    *reinterpret_cast<float4*>(&As[1][1][lr][lc]) = cvt4(pa1);
    *reinterpret_cast<float4*>(&Bs[1][0][lr][lc]) = cvt4(pb0);
    *reinterpret_cast<float4*>(&Bs[1][1][lr][lc]) = cvt4(pb1);
    __syncthreads();

    for (int s = 1; s <= 16; s++) {
        int cur = s & 1;
        int nxt = cur ^ 1;
        bool has_next = (s < 16);

        if (has_next) {
            pa0 = *reinterpret_cast<const float4*>(Ax + (2 * s    ) * BK);
            pa1 = *reinterpret_cast<const float4*>(Ax + (2 * s + 1) * BK);
            pb0 = *reinterpret_cast<const float4*>(Bw + (2 * s + 1) * BK);
            pb1 = *reinterpret_cast<const float4*>(Bw + (2 * s + 2) * BK);
        }

#pragma unroll
        for (int sub = 0; sub < 2; sub++) {
            uint32_t afr[4][4], bfr[4][2];
#pragma unroll
            for (int ma = 0; ma < 4; ma++) {
                int r0 = warp_m + ma * 16 + g;
                afr[ma][0] = __float_as_uint(As[cur][sub][r0    ][q    ]);
                afr[ma][1] = __float_as_uint(As[cur][sub][r0 + 8][q    ]);
                afr[ma][2] = __float_as_uint(As[cur][sub][r0    ][q + 4]);
                afr[ma][3] = __float_as_uint(As[cur][sub][r0 + 8][q + 4]);
            }
#pragma unroll
            for (int nb = 0; nb < 4; nb++) {
                int c0 = warp_n + nb * 8 + g;
                bfr[nb][0] = __float_as_uint(Bs[cur][sub][c0][q    ]);
                bfr[nb][1] = __float_as_uint(Bs[cur][sub][c0][q + 4]);
            }
#pragma unroll
            for (int ma = 0; ma < 4; ma++)
#pragma unroll
                for (int nb = 0; nb < 4; nb++)
                    mma_tf32(acc[ma][nb], afr[ma], bfr[nb]);
        }

        if (has_next) {
            *reinterpret_cast<float4*>(&As[nxt][0][lr][lc]) = cvt4(pa0);
            *reinterpret_cast<float4*>(&As[nxt][1][lr][lc]) = cvt4(pa1);
            *reinterpret_cast<float4*>(&Bs[nxt][0][lr][lc]) = cvt4(pb0);
            *reinterpret_cast<float4*>(&Bs[nxt][1][lr][lc]) = cvt4(pb1);
            __syncthreads();
        }
    }

    // epilogue
#pragma unroll
    for (int ma = 0; ma < 4; ma++) {
#pragma unroll
        for (int nb = 0; nb < 4; nb++) {
            int col  = colBase + warp_n + nb * 8 + 2 * q;
            int row0 = rowBase + warp_m + ma * 16 + g;
            float bias0 = __ldg(b2 + col);
            float bias1 = __ldg(b2 + col + 1);
            float2 v0 = make_float2(acc[ma][nb][0] + bias0, acc[ma][nb][1] + bias1);
            float2 v1 = make_float2(acc[ma][nb][2] + bias0, acc[ma][nb][3] + bias1);
            *reinterpret_cast<float2*>(out + (size_t)row0 * EDIM + col)       = v0;
            *reinterpret_cast<float2*>(out + (size_t)(row0 + 8) * EDIM + col) = v1;
        }
    }
}

// ---------------------------------------------------------------------------
extern "C" void kernel_launch(void* const* d_in, const int* in_sizes, int n_in,
                              void* d_out, int out_size) {
    const float* x  = (const float*)d_in[0];
    const float* W1 = (const float*)d_in[1];
    const float* b1 = (const float*)d_in[2];
    const float* qw = (const float*)d_in[3];
    const float* W2 = (const float*)d_in[4];
    const float* b2 = (const float*)d_in[5];
    float* out = (float*)d_out;

    quantum_kernel<<<NROWS / 32, 256>>>(x, W1, b1, qw);

    dim3 grid(NROWS / BM, EDIM / BN);
    gemm_kernel<<<grid, 256>>>(x, W2, b2, out);
}